// round 2
// baseline (speedup 1.0000x reference)
#include <cuda_runtime.h>
#include <cuda_fp16.h>

// QLSTM: T=512, B=256, D=128, H=256, P=128. GAMMA=1.
// Persistent batch-parallel kernel: 128 CTAs x 2 batch rows, zero inter-CTA comm.

#define T_STEPS 512
#define BATCH   256
#define DIN     128
#define HID     256
#define PROTO   128
#define DH      384   // DIN + HID
#define DH2     192   // DH/2
#define GATES4  1024  // 4*HID
#define BC      2
#define NCTA    (BATCH / BC)   // 128
#define NTHREADS 256

// Preprocessed weights (built once per launch by prep_kernel)
__device__ __half2 g_protoT2[DH2 * PROTO];   // [d2][p]: (proto[p][2d2], proto[p][2d2+1])
__device__ float   g_pnorm[PROTO];           // ||proto[p]||^2
__device__ __half  g_WallT[PROTO * GATES4];  // [p][j], j = gate*256 + h

__global__ void prep_kernel(const float* __restrict__ proto,
                            const float* __restrict__ Wf, const float* __restrict__ Wi,
                            const float* __restrict__ Wg, const float* __restrict__ Wo) {
    int tid = blockIdx.x * blockDim.x + threadIdx.x;
    int nth = gridDim.x * blockDim.x;
    for (int idx = tid; idx < PROTO * GATES4; idx += nth) {
        int p = idx >> 10;
        int j = idx & 1023;
        int g = j >> 8;
        int h = j & 255;
        const float* W = (g == 0) ? Wf : (g == 1) ? Wi : (g == 2) ? Wg : Wo;
        g_WallT[idx] = __float2half(W[h * PROTO + p]);
    }
    for (int idx = tid; idx < DH2 * PROTO; idx += nth) {
        int p  = idx & (PROTO - 1);
        int d2 = idx >> 7;
        float a = proto[p * DH + 2 * d2];
        float b = proto[p * DH + 2 * d2 + 1];
        g_protoT2[idx] = __floats2half2_rn(a, b);
    }
    for (int p = tid; p < PROTO; p += nth) {
        float s = 0.f;
        for (int d = 0; d < DH; d++) { float v = proto[p * DH + d]; s += v * v; }
        g_pnorm[p] = s;
    }
}

struct Smem {
    __half2 protoT2[DH2 * PROTO];   // 98304 B
    float   pnorm[PROTO];           // 512 B
    float   comb[BC][DH];           // [b][x(128) | h(256)]  3072 B
    float   csm[BC][HID];           // 2048 B
    float   ksm[BC][PROTO];         // 1024 B
    float   gsm[4][BC][HID];        // 8192 B (activated gates f,i,g,o)
    float   bsm[GATES4];            // 4096 B (biases, j = gate*256+h)
};

__device__ __forceinline__ float fast_sigmoid(float z) {
    return __fdividef(1.0f, 1.0f + __expf(-z));
}
__device__ __forceinline__ float fast_tanh(float z) {
    float r;
    asm("tanh.approx.f32 %0, %1;" : "=f"(r) : "f"(z));
    return r;
}

__global__ __launch_bounds__(NTHREADS, 1)
void qlstm_kernel(const float* __restrict__ x,
                  const float* __restrict__ bf, const float* __restrict__ bi,
                  const float* __restrict__ bg, const float* __restrict__ bo,
                  float* __restrict__ out) {
    extern __shared__ char smem_raw[];
    Smem& s = *reinterpret_cast<Smem*>(smem_raw);

    const int t    = threadIdx.x;
    const int cta  = blockIdx.x;
    const int wid  = t >> 5;
    const int lane = t & 31;

    // ---- one-time CTA init ----
    for (int i = t; i < DH2 * PROTO; i += NTHREADS) s.protoT2[i] = g_protoT2[i];
    for (int i = t; i < PROTO; i += NTHREADS)       s.pnorm[i]   = g_pnorm[i];
    for (int i = t; i < GATES4; i += NTHREADS) {
        int g = i >> 8, h = i & 255;
        const float* bb = (g == 0) ? bf : (g == 1) ? bi : (g == 2) ? bg : bo;
        s.bsm[i] = bb[h];
    }
    for (int i = t; i < BC * HID; i += NTHREADS) {
        int b = i >> 8, h = i & 255;
        s.comb[b][DIN + h] = 0.f;          // h0 = 0
        (&s.csm[0][0])[i]  = 0.f;          // c0 = 0
    }
    __syncthreads();

    const int pb = t >> 7;      // phase-1 batch row (0/1)
    const int pp = t & 127;     // phase-1 prototype index
    const int cb_warp = wid >> 2; // cnorm batch row for this warp (warps 0-3 -> b0)

    const int j0 = 4 * t;            // phase-2/3: this thread's 4 gate columns
    const int gate = j0 >> 8;        // which gate (0..3)
    const int h0 = j0 & 255;         // h base within gate

    for (int step = 0; step < T_STEPS; step++) {
        // ---- phase 0: load x_t into comb[.][0:128] ----
        {
            int b = t >> 7, d = t & 127;
            s.comb[b][d] = x[((size_t)step * BATCH + (size_t)(cta * BC + b)) * DIN + d];
        }
        __syncthreads();

        // ---- per-warp redundant cnorm (no extra barriers) ----
        float cn = 0.f;
        #pragma unroll
        for (int i = 0; i < 12; i++) {
            float v = s.comb[cb_warp][lane * 12 + i];
            cn = fmaf(v, v, cn);
        }
        #pragma unroll
        for (int o = 16; o; o >>= 1) cn += __shfl_xor_sync(0xffffffffu, cn, o);
        // all lanes of warp now hold ||comb[cb_warp]||^2 ; cb_warp == pb for every thread

        // ---- phase 1: dot(comb[pb], proto[pp]) over 384 dims ----
        float acc = 0.f;
        {
            const float2*  cb2 = reinterpret_cast<const float2*>(&s.comb[pb][0]);
            const __half2* pr  = s.protoT2;
            #pragma unroll 8
            for (int d2 = 0; d2 < DH2; d2++) {
                float2 c2 = cb2[d2];
                float2 p2 = __half22float2(pr[d2 * PROTO + pp]);
                acc = fmaf(c2.x, p2.x, acc);
                acc = fmaf(c2.y, p2.y, acc);
            }
        }
        float dist = cn - 2.f * acc + s.pnorm[pp];   // GAMMA = 1
        s.ksm[pb][pp] = __expf(-dist);
        __syncthreads();

        // ---- phase 2: gates = k @ WallT  (each thread: 4 cols x 2 batch rows) ----
        float a00 = 0.f, a01 = 0.f, a02 = 0.f, a03 = 0.f;
        float a10 = 0.f, a11 = 0.f, a12 = 0.f, a13 = 0.f;
        {
            const __half* wbase = g_WallT + j0;
            #pragma unroll 8
            for (int p = 0; p < PROTO; p++) {
                uint2 w = *reinterpret_cast<const uint2*>(wbase + (size_t)p * GATES4);
                float2 f01 = __half22float2(*reinterpret_cast<const __half2*>(&w.x));
                float2 f23 = __half22float2(*reinterpret_cast<const __half2*>(&w.y));
                float k0 = s.ksm[0][p];
                float k1 = s.ksm[1][p];
                a00 = fmaf(k0, f01.x, a00); a01 = fmaf(k0, f01.y, a01);
                a02 = fmaf(k0, f23.x, a02); a03 = fmaf(k0, f23.y, a03);
                a10 = fmaf(k1, f01.x, a10); a11 = fmaf(k1, f01.y, a11);
                a12 = fmaf(k1, f23.x, a12); a13 = fmaf(k1, f23.y, a13);
            }
        }

        // ---- phase 3a: bias + activation, write to gsm ----
        {
            float z[8] = { a00, a01, a02, a03, a10, a11, a12, a13 };
            #pragma unroll
            for (int i = 0; i < 4; i++) {
                float bia = s.bsm[j0 + i];
                float z0 = z[i]     + bia;
                float z1 = z[4 + i] + bia;
                float v0, v1;
                if (gate == 2) { v0 = fast_tanh(z0);    v1 = fast_tanh(z1); }
                else           { v0 = fast_sigmoid(z0); v1 = fast_sigmoid(z1); }
                s.gsm[gate][0][h0 + i] = v0;
                s.gsm[gate][1][h0 + i] = v1;
            }
        }
        __syncthreads();

        // ---- phase 3b: cell update + output write ----
        {
            size_t outbase = (size_t)step * BATCH * HID;
            #pragma unroll
            for (int b = 0; b < BC; b++) {
                int h = t;
                float fg = s.gsm[0][b][h];
                float ig = s.gsm[1][b][h];
                float gg = s.gsm[2][b][h];
                float og = s.gsm[3][b][h];
                float c  = fmaf(fg, s.csm[b][h], ig * gg);
                s.csm[b][h] = c;
                float hn = og * fast_tanh(c);
                s.comb[b][DIN + h] = hn;
                out[outbase + (size_t)(cta * BC + b) * HID + h] = hn;
            }
        }
        __syncthreads();
    }

    // ---- final hx, cx ----
    {
        size_t base = (size_t)T_STEPS * BATCH * HID;
        #pragma unroll
        for (int b = 0; b < BC; b++) {
            int bg_ = cta * BC + b;
            out[base + (size_t)bg_ * HID + t]                      = s.comb[b][DIN + t];
            out[base + (size_t)BATCH * HID + (size_t)bg_ * HID + t] = s.csm[b][t];
        }
    }
}

extern "C" void kernel_launch(void* const* d_in, const int* in_sizes, int n_in,
                              void* d_out, int out_size) {
    const float* x     = (const float*)d_in[0];
    const float* proto = (const float*)d_in[1];
    const float* Wf    = (const float*)d_in[2];
    const float* bf    = (const float*)d_in[3];
    const float* Wi    = (const float*)d_in[4];
    const float* bi    = (const float*)d_in[5];
    const float* Wg    = (const float*)d_in[6];
    const float* bg    = (const float*)d_in[7];
    const float* Wo    = (const float*)d_in[8];
    const float* bo    = (const float*)d_in[9];
    float* out = (float*)d_out;

    cudaFuncSetAttribute(qlstm_kernel, cudaFuncAttributeMaxDynamicSharedMemorySize,
                         (int)sizeof(Smem));

    prep_kernel<<<128, 256>>>(proto, Wf, Wi, Wg, Wo);
    qlstm_kernel<<<NCTA, NTHREADS, sizeof(Smem)>>>(x, bf, bi, bg, bo, out);
}

// round 6
// speedup vs baseline: 1.4500x; 1.4500x over previous
#include <cuda_runtime.h>
#include <cuda_fp16.h>
#include <cstdint>

// QLSTM: T=512, B=256, D=128, H=256, P=128. GAMMA=1.
// 128 persistent CTAs x 2 batch rows, 1024 threads (32 warps) each.
// Phase 1 (RBF distances): 8-way chunk split over the 384-dim dot.
// Phase 2 (gate GEMM):     4-way split over the 128 prototypes;
//                          first 32 p-rows of W live in SMEM, rest stream from L2.

#define T_STEPS 512
#define BATCH   256
#define DIN     128
#define HID     256
#define PROTO   128
#define DH      384
#define DH2     192
#define GATES4  1024
#define BC      2
#define NCTA    (BATCH / BC)
#define NTHREADS 1024
#define PS      32            // p-rows of W resident in SMEM

// Preprocessed weights (built once per launch)
__device__ __half2 g_protoT2[DH2 * PROTO];   // [d2][p]
__device__ float   g_pnorm[PROTO];
__device__ __half  g_WallT[PROTO * GATES4];  // [p][j], j = gate*256 + h

__global__ void prep_kernel(const float* __restrict__ proto,
                            const float* __restrict__ Wf, const float* __restrict__ Wi,
                            const float* __restrict__ Wg, const float* __restrict__ Wo) {
    int tid = blockIdx.x * blockDim.x + threadIdx.x;
    int nth = gridDim.x * blockDim.x;
    for (int idx = tid; idx < PROTO * GATES4; idx += nth) {
        int p = idx >> 10;
        int j = idx & 1023;
        int g = j >> 8;
        int h = j & 255;
        const float* W = (g == 0) ? Wf : (g == 1) ? Wi : (g == 2) ? Wg : Wo;
        g_WallT[idx] = __float2half(W[h * PROTO + p]);
    }
    for (int idx = tid; idx < DH2 * PROTO; idx += nth) {
        int p  = idx & (PROTO - 1);
        int d2 = idx >> 7;
        float a = proto[p * DH + 2 * d2];
        float b = proto[p * DH + 2 * d2 + 1];
        g_protoT2[idx] = __floats2half2_rn(a, b);
    }
    for (int p = tid; p < PROTO; p += nth) {
        float s = 0.f;
        for (int d = 0; d < DH; d++) { float v = proto[p * DH + d]; s += v * v; }
        g_pnorm[p] = s;
    }
}

struct Smem {
    __half2 protoT2[DH2 * PROTO];     // 98304 B
    __half  Wsm[PS * GATES4];         // 65536 B  (first PS p-rows of g_WallT)
    union {
        float2 part1[8][PROTO];       // 8 KB   (chunk, p) -> (dot_b0, dot_b1)
        float4 part2[4][256][2];      // 32 KB  (pg, colquad) -> 2x float4 accums
    } u;
    float comb[BC][DH];               // 3072 B  [b][ x(128) | h(256) ]
    float csm[BC][HID];               // 2048 B
    float2 ksm2[PROTO];               // 1024 B  (k_b0, k_b1)
    float gsm[4][BC][HID];            // 8192 B
    float bsm[GATES4];                // 4096 B
    float pnorm[PROTO];               // 512 B
    float cn[BC];                     // 8 B
};                                    // ~210.5 KB total

__device__ __forceinline__ float fast_sigmoid(float z) {
    return __fdividef(1.0f, 1.0f + __expf(-z));
}
__device__ __forceinline__ float fast_tanh(float z) {
    float r;
    asm("tanh.approx.f32 %0, %1;" : "=f"(r) : "f"(z));
    return r;
}

__global__ __launch_bounds__(NTHREADS, 1)
void qlstm_kernel(const float* __restrict__ x,
                  const float* __restrict__ bf, const float* __restrict__ bi,
                  const float* __restrict__ bg, const float* __restrict__ bo,
                  float* __restrict__ out) {
    extern __shared__ char smem_raw[];
    Smem& s = *reinterpret_cast<Smem*>(smem_raw);

    const int t   = threadIdx.x;
    const int cta = blockIdx.x;
    const int wid  = t >> 5;
    const int lane = t & 31;

    // ---- one-time CTA init ----
    {
        const unsigned int* psrc = reinterpret_cast<const unsigned int*>(g_protoT2);
        unsigned int*       pdst = reinterpret_cast<unsigned int*>(s.protoT2);
        for (int i = t; i < DH2 * PROTO; i += NTHREADS) pdst[i] = psrc[i];
        const unsigned int* wsrc = reinterpret_cast<const unsigned int*>(g_WallT);
        unsigned int*       wdst = reinterpret_cast<unsigned int*>(s.Wsm);
        for (int i = t; i < PS * GATES4 / 2; i += NTHREADS) wdst[i] = wsrc[i];
        for (int i = t; i < PROTO; i += NTHREADS) s.pnorm[i] = g_pnorm[i];
        for (int i = t; i < GATES4; i += NTHREADS) {
            int g = i >> 8, h = i & 255;
            const float* bb = (g == 0) ? bf : (g == 1) ? bi : (g == 2) ? bg : bo;
            s.bsm[i] = bb[h];
        }
        for (int i = t; i < BC * HID; i += NTHREADS) {
            int b = i >> 8, h = i & 255;
            s.comb[b][DIN + h] = 0.f;
            s.csm[b][h]        = 0.f;
        }
    }
    __syncthreads();

    // phase-1 partial mapping
    const int chunk = t >> 7;        // 0..7  (24 d2 each)
    const int pp    = t & 127;       // prototype
    // phase-2 mapping
    const int pg    = t >> 8;        // 0..3  (32 p each)
    const int jq    = t & 255;       // column quad
    const int j0    = jq * 4;
    const int gate  = j0 >> 8;
    const int h0    = j0 & 255;

    for (int step = 0; step < T_STEPS; step++) {
        // ---- phase 0: load x_t ----
        if (t < BC * DIN) {
            int b = t >> 7, d = t & 127;
            s.comb[b][d] = x[((size_t)step * BATCH + (size_t)(cta * BC + b)) * DIN + d];
        }
        __syncthreads();   // S0

        // ---- cnorm (warps 0,1) ----
        if (wid < 2) {
            float cn = 0.f;
            const float* cb = s.comb[wid];
            #pragma unroll
            for (int i = 0; i < 12; i++) { float v = cb[lane * 12 + i]; cn = fmaf(v, v, cn); }
            #pragma unroll
            for (int o = 16; o; o >>= 1) cn += __shfl_xor_sync(0xffffffffu, cn, o);
            if (lane == 0) s.cn[wid] = cn;
        }

        // ---- phase 1 partial: 24 d2 per thread, both rows ----
        {
            float a0 = 0.f, a1 = 0.f;
            const float2* c0 = reinterpret_cast<const float2*>(&s.comb[0][0]) + chunk * 24;
            const float2* c1 = reinterpret_cast<const float2*>(&s.comb[1][0]) + chunk * 24;
            const __half2* pr = s.protoT2 + chunk * 24 * PROTO + pp;
            #pragma unroll
            for (int i = 0; i < 24; i++) {
                float2 pf = __half22float2(pr[i * PROTO]);
                float2 u0 = c0[i];
                float2 u1 = c1[i];
                a0 = fmaf(pf.x, u0.x, a0); a0 = fmaf(pf.y, u0.y, a0);
                a1 = fmaf(pf.x, u1.x, a1); a1 = fmaf(pf.y, u1.y, a1);
            }
            s.u.part1[chunk][pp] = make_float2(a0, a1);
        }
        __syncthreads();   // S1

        // ---- phase 1 combine: k = exp(2*dot - cnorm - pnorm) ----
        if (t < PROTO) {
            float d0 = 0.f, d1 = 0.f;
            #pragma unroll
            for (int c = 0; c < 8; c++) { float2 v = s.u.part1[c][t]; d0 += v.x; d1 += v.y; }
            float pn = s.pnorm[t];
            float k0 = __expf(2.f * d0 - s.cn[0] - pn);
            float k1 = __expf(2.f * d1 - s.cn[1] - pn);
            s.ksm2[t] = make_float2(k0, k1);
        }
        __syncthreads();   // S2

        // ---- phase 2 partial: 4 cols x 32 p per thread ----
        {
            float a00 = 0.f, a01 = 0.f, a02 = 0.f, a03 = 0.f;
            float a10 = 0.f, a11 = 0.f, a12 = 0.f, a13 = 0.f;
            const int pbase = pg * 32;
            if (pg == 0) {
                const __half* wb = s.Wsm + j0;
                #pragma unroll 4
                for (int i = 0; i < 32; i++) {
                    int p = pbase + i;
                    uint2 w = *reinterpret_cast<const uint2*>(wb + p * GATES4);
                    float2 f01 = __half22float2(*reinterpret_cast<const __half2*>(&w.x));
                    float2 f23 = __half22float2(*reinterpret_cast<const __half2*>(&w.y));
                    float2 k = s.ksm2[p];
                    a00 = fmaf(k.x, f01.x, a00); a01 = fmaf(k.x, f01.y, a01);
                    a02 = fmaf(k.x, f23.x, a02); a03 = fmaf(k.x, f23.y, a03);
                    a10 = fmaf(k.y, f01.x, a10); a11 = fmaf(k.y, f01.y, a11);
                    a12 = fmaf(k.y, f23.x, a12); a13 = fmaf(k.y, f23.y, a13);
                }
            } else {
                const __half* wb = g_WallT + j0;
                #pragma unroll 4
                for (int i = 0; i < 32; i++) {
                    int p = pbase + i;
                    uint2 w = *reinterpret_cast<const uint2*>(wb + (size_t)p * GATES4);
                    float2 f01 = __half22float2(*reinterpret_cast<const __half2*>(&w.x));
                    float2 f23 = __half22float2(*reinterpret_cast<const __half2*>(&w.y));
                    float2 k = s.ksm2[p];
                    a00 = fmaf(k.x, f01.x, a00); a01 = fmaf(k.x, f01.y, a01);
                    a02 = fmaf(k.x, f23.x, a02); a03 = fmaf(k.x, f23.y, a03);
                    a10 = fmaf(k.y, f01.x, a10); a11 = fmaf(k.y, f01.y, a11);
                    a12 = fmaf(k.y, f23.x, a12); a13 = fmaf(k.y, f23.y, a13);
                }
            }
            s.u.part2[pg][jq][0] = make_float4(a00, a01, a02, a03);
            s.u.part2[pg][jq][1] = make_float4(a10, a11, a12, a13);
        }
        __syncthreads();   // S3

        // ---- phase 2 combine + activation ----
        if (t < 256) {
            float4 z0 = s.u.part2[0][t][0];
            float4 z1 = s.u.part2[0][t][1];
            #pragma unroll
            for (int g = 1; g < 4; g++) {
                float4 v0 = s.u.part2[g][t][0];
                float4 v1 = s.u.part2[g][t][1];
                z0.x += v0.x; z0.y += v0.y; z0.z += v0.z; z0.w += v0.w;
                z1.x += v1.x; z1.y += v1.y; z1.z += v1.z; z1.w += v1.w;
            }
            float zb0[4] = { z0.x, z0.y, z0.z, z0.w };
            float zb1[4] = { z1.x, z1.y, z1.z, z1.w };
            #pragma unroll
            for (int i = 0; i < 4; i++) {
                float bia = s.bsm[j0 + i];
                float w0 = zb0[i] + bia;
                float w1 = zb1[i] + bia;
                float v0, v1;
                if (gate == 2) { v0 = fast_tanh(w0);    v1 = fast_tanh(w1); }
                else           { v0 = fast_sigmoid(w0); v1 = fast_sigmoid(w1); }
                s.gsm[gate][0][h0 + i] = v0;
                s.gsm[gate][1][h0 + i] = v1;
            }
        }
        __syncthreads();   // S4

        // ---- phase 3: cell update + output ----
        if (t < BC * HID) {
            int b = t >> 8, h = t & 255;
            float fg = s.gsm[0][b][h];
            float ig = s.gsm[1][b][h];
            float gg = s.gsm[2][b][h];
            float og = s.gsm[3][b][h];
            float c  = fmaf(fg, s.csm[b][h], ig * gg);
            s.csm[b][h] = c;
            float hn = og * fast_tanh(c);
            s.comb[b][DIN + h] = hn;
            out[(size_t)step * BATCH * HID + (size_t)(cta * BC + b) * HID + h] = hn;
        }
        // loop wraps: x-load writes comb[.][0:128] (disjoint from phase-3 writes),
        // then S0 orders everything before phase-1 reads.
    }

    // ---- final hx, cx (same thread mapping as phase 3, no sync needed) ----
    if (t < BC * HID) {
        int b = t >> 8, h = t & 255;
        int bgl = cta * BC + b;
        size_t base = (size_t)T_STEPS * BATCH * HID;
        out[base + (size_t)bgl * HID + h]                        = s.comb[b][DIN + h];
        out[base + (size_t)BATCH * HID + (size_t)bgl * HID + h]  = s.csm[b][h];
    }
}

extern "C" void kernel_launch(void* const* d_in, const int* in_sizes, int n_in,
                              void* d_out, int out_size) {
    const float* x     = (const float*)d_in[0];
    const float* proto = (const float*)d_in[1];
    const float* Wf    = (const float*)d_in[2];
    const float* bf    = (const float*)d_in[3];
    const float* Wi    = (const float*)d_in[4];
    const float* bi    = (const float*)d_in[5];
    const float* Wg    = (const float*)d_in[6];
    const float* bg    = (const float*)d_in[7];
    const float* Wo    = (const float*)d_in[8];
    const float* bo    = (const float*)d_in[9];
    float* out = (float*)d_out;

    cudaFuncSetAttribute(qlstm_kernel, cudaFuncAttributeMaxDynamicSharedMemorySize,
                         (int)sizeof(Smem));

    prep_kernel<<<128, 256>>>(proto, Wf, Wi, Wg, Wo);
    qlstm_kernel<<<NCTA, NTHREADS, sizeof(Smem)>>>(x, bf, bi, bg, bo, out);
}

// round 7
// speedup vs baseline: 1.8753x; 1.2933x over previous
#include <cuda_runtime.h>
#include <cuda_fp16.h>
#include <cstdint>

// QLSTM: T=512, B=256, D=128, H=256, P=128. GAMMA=1.
// 128 persistent CTAs x 2 batch rows, 1024 threads each.
// R6: HFMA2 (packed fp16) math in phases 1&2, wider LDS, spread combines.

#define T_STEPS 512
#define BATCH   256
#define DIN     128
#define HID     256
#define PROTO   128
#define DH      384
#define DH2     192          // DH/2 (half2 count per row)
#define QP      96           // DH2/2 (proto half2-pair count)
#define GATES4  1024
#define BC      2
#define NCTA    (BATCH / BC)
#define NTHREADS 1024
#define PS      32           // p-rows of W resident in SMEM

__device__ uint2  g_protoP2[QP * PROTO];     // [q][p]: {half2(d4q,d4q+1), half2(d4q+2,d4q+3)}
__device__ float  g_pnorm[PROTO];
__device__ __half g_WallT[PROTO * GATES4];   // [p][j], j = gate*256 + h

__global__ void prep_kernel(const float* __restrict__ proto,
                            const float* __restrict__ Wf, const float* __restrict__ Wi,
                            const float* __restrict__ Wg, const float* __restrict__ Wo) {
    int tid = blockIdx.x * blockDim.x + threadIdx.x;
    int nth = gridDim.x * blockDim.x;
    for (int idx = tid; idx < PROTO * GATES4; idx += nth) {
        int p = idx >> 10;
        int j = idx & 1023;
        int g = j >> 8;
        int h = j & 255;
        const float* W = (g == 0) ? Wf : (g == 1) ? Wi : (g == 2) ? Wg : Wo;
        g_WallT[idx] = __float2half(W[h * PROTO + p]);
    }
    for (int idx = tid; idx < QP * PROTO; idx += nth) {
        int p = idx & (PROTO - 1);
        int q = idx >> 7;
        __half2 a = __floats2half2_rn(proto[p * DH + 4 * q],     proto[p * DH + 4 * q + 1]);
        __half2 b = __floats2half2_rn(proto[p * DH + 4 * q + 2], proto[p * DH + 4 * q + 3]);
        uint2 v;
        v.x = *reinterpret_cast<unsigned int*>(&a);
        v.y = *reinterpret_cast<unsigned int*>(&b);
        g_protoP2[idx] = v;
    }
    for (int p = tid; p < PROTO; p += nth) {
        float s = 0.f;
        for (int d = 0; d < DH; d++) { float v = proto[p * DH + d]; s += v * v; }
        g_pnorm[p] = s;
    }
}

struct Smem {
    uint2   protoP2[QP * PROTO];      // 98304 B
    __half  Wsm[PS * GATES4];         // 65536 B
    union {
        float part1[8][2][PROTO];     // 8 KB   (chunk, row, p)
        float part2[4][2][GATES4];    // 32 KB  (pg, row, col)
    } u;
    float  comb[BC][DH];              // 3072 B  fp32 (cnorm + final output)
    __half combh[BC][DH];             // 1536 B  fp16 mirror for phase 1
    float  csm[BC][HID];              // 2048 B
    __half2 kh[BC][PROTO];            // 1024 B  (k,k) duplicated
    float  gsm[4][BC][HID];           // 8192 B
    float  bsm[GATES4];               // 4096 B
    float  pnorm[PROTO];              // 512 B
    float  cn[BC];                    // 8 B
};                                    // ~212 KB

__device__ __forceinline__ float fast_sigmoid(float z) {
    return __fdividef(1.0f, 1.0f + __expf(-z));
}
__device__ __forceinline__ float fast_tanh(float z) {
    float r;
    asm("tanh.approx.f32 %0, %1;" : "=f"(r) : "f"(z));
    return r;
}
__device__ __forceinline__ __half2 u2h(unsigned int v) {
    return *reinterpret_cast<__half2*>(&v);
}

__global__ __launch_bounds__(NTHREADS, 1)
void qlstm_kernel(const float* __restrict__ x,
                  const float* __restrict__ bf, const float* __restrict__ bi,
                  const float* __restrict__ bg, const float* __restrict__ bo,
                  float* __restrict__ out) {
    extern __shared__ char smem_raw[];
    Smem& s = *reinterpret_cast<Smem*>(smem_raw);

    const int t   = threadIdx.x;
    const int cta = blockIdx.x;
    const int wid  = t >> 5;
    const int lane = t & 31;

    // ---- one-time CTA init ----
    {
        for (int i = t; i < QP * PROTO; i += NTHREADS) s.protoP2[i] = g_protoP2[i];
        const unsigned int* wsrc = reinterpret_cast<const unsigned int*>(g_WallT);
        unsigned int*       wdst = reinterpret_cast<unsigned int*>(s.Wsm);
        for (int i = t; i < PS * GATES4 / 2; i += NTHREADS) wdst[i] = wsrc[i];
        for (int i = t; i < PROTO; i += NTHREADS) s.pnorm[i] = g_pnorm[i];
        for (int i = t; i < GATES4; i += NTHREADS) {
            int g = i >> 8, h = i & 255;
            const float* bb = (g == 0) ? bf : (g == 1) ? bi : (g == 2) ? bg : bo;
            s.bsm[i] = bb[h];
        }
        for (int i = t; i < BC * HID; i += NTHREADS) {
            int b = i >> 8, h = i & 255;
            s.comb[b][DIN + h]  = 0.f;
            s.combh[b][DIN + h] = __float2half(0.f);
            s.csm[b][h]         = 0.f;
        }
    }
    __syncthreads();

    // phase-1 mapping: 8 chunks x 128 protos (chunk = 24 half2 = 48 dims)
    const int chunk = t >> 7;
    const int pp    = t & 127;
    // phase-2 mapping: 4 p-groups x 256 col-quads
    const int pg    = t >> 8;
    const int jq    = t & 255;
    const int j0    = jq * 4;

    for (int step = 0; step < T_STEPS; step++) {
        // ---- phase 0: load x_t (128 threads, float2 each) ----
        if (t < 128) {
            int b = t >> 6, i2 = t & 63;
            const float2 v = *reinterpret_cast<const float2*>(
                x + ((size_t)step * BATCH + (size_t)(cta * BC + b)) * DIN + 2 * i2);
            reinterpret_cast<float2*>(&s.comb[b][0])[i2] = v;
            reinterpret_cast<__half2*>(&s.combh[b][0])[i2] = __floats2half2_rn(v.x, v.y);
        }
        __syncthreads();   // S0

        // ---- cnorm (warps 0,1; fp32) ----
        if (wid < 2) {
            float cn = 0.f;
            const float* cb = s.comb[wid];
            #pragma unroll
            for (int i = 0; i < 12; i++) { float v = cb[lane * 12 + i]; cn = fmaf(v, v, cn); }
            #pragma unroll
            for (int o = 16; o; o >>= 1) cn += __shfl_xor_sync(0xffffffffu, cn, o);
            if (lane == 0) s.cn[wid] = cn;
        }

        // ---- phase 1 partial: 24 half2 per thread per row, HFMA2 ----
        {
            __half2 acc0 = __float2half2_rn(0.f);
            __half2 acc1 = __float2half2_rn(0.f);
            const uint4* cb0 = reinterpret_cast<const uint4*>(&s.combh[0][0]) + chunk * 6;
            const uint4* cb1 = reinterpret_cast<const uint4*>(&s.combh[1][0]) + chunk * 6;
            const uint2* pr  = s.protoP2 + (chunk * 12) * PROTO + pp;
            #pragma unroll
            for (int i = 0; i < 6; i++) {
                uint4 c0 = cb0[i];
                uint4 c1 = cb1[i];
                uint2 w0 = pr[(2 * i) * PROTO];
                uint2 w1 = pr[(2 * i + 1) * PROTO];
                acc0 = __hfma2(u2h(c0.x), u2h(w0.x), acc0);
                acc0 = __hfma2(u2h(c0.y), u2h(w0.y), acc0);
                acc0 = __hfma2(u2h(c0.z), u2h(w1.x), acc0);
                acc0 = __hfma2(u2h(c0.w), u2h(w1.y), acc0);
                acc1 = __hfma2(u2h(c1.x), u2h(w0.x), acc1);
                acc1 = __hfma2(u2h(c1.y), u2h(w0.y), acc1);
                acc1 = __hfma2(u2h(c1.z), u2h(w1.x), acc1);
                acc1 = __hfma2(u2h(c1.w), u2h(w1.y), acc1);
            }
            float2 f0 = __half22float2(acc0);
            float2 f1 = __half22float2(acc1);
            s.u.part1[chunk][0][pp] = f0.x + f0.y;
            s.u.part1[chunk][1][pp] = f1.x + f1.y;
        }
        __syncthreads();   // S1

        // ---- phase 1 combine (256 threads): k = exp(2*dot - cnorm - pnorm) ----
        if (t < 2 * PROTO) {
            int r = t >> 7, p = t & 127;
            float d = 0.f;
            #pragma unroll
            for (int c = 0; c < 8; c++) d += s.u.part1[c][r][p];
            float k = __expf(2.f * d - s.cn[r] - s.pnorm[p]);
            s.kh[r][p] = __float2half2_rn(k);   // (k,k)
        }
        __syncthreads();   // S2

        // ---- phase 2 partial: 4 cols x 32 p per thread, HFMA2 ----
        {
            __half2 b0_01 = __float2half2_rn(0.f), b0_23 = b0_01;
            __half2 b1_01 = b0_01, b1_23 = b0_01;
            const int pbase = pg * 32;
            const __half2* k0p = &s.kh[0][pbase];
            const __half2* k1p = &s.kh[1][pbase];
            if (pg == 0) {
                const uint2* wb = reinterpret_cast<const uint2*>(s.Wsm) + jq;
                #pragma unroll 8
                for (int i = 0; i < 32; i++) {
                    uint2 w = wb[(pbase + i) * 256];
                    __half2 k0 = k0p[i];
                    __half2 k1 = k1p[i];
                    b0_01 = __hfma2(k0, u2h(w.x), b0_01);
                    b0_23 = __hfma2(k0, u2h(w.y), b0_23);
                    b1_01 = __hfma2(k1, u2h(w.x), b1_01);
                    b1_23 = __hfma2(k1, u2h(w.y), b1_23);
                }
            } else {
                const uint2* wb = reinterpret_cast<const uint2*>(g_WallT) + jq;
                #pragma unroll 8
                for (int i = 0; i < 32; i++) {
                    uint2 w = wb[(size_t)(pbase + i) * 256];
                    __half2 k0 = k0p[i];
                    __half2 k1 = k1p[i];
                    b0_01 = __hfma2(k0, u2h(w.x), b0_01);
                    b0_23 = __hfma2(k0, u2h(w.y), b0_23);
                    b1_01 = __hfma2(k1, u2h(w.x), b1_01);
                    b1_23 = __hfma2(k1, u2h(w.y), b1_23);
                }
            }
            float2 r01 = __half22float2(b0_01);
            float2 r23 = __half22float2(b0_23);
            *reinterpret_cast<float4*>(&s.u.part2[pg][0][j0]) =
                make_float4(r01.x, r01.y, r23.x, r23.y);
            r01 = __half22float2(b1_01);
            r23 = __half22float2(b1_23);
            *reinterpret_cast<float4*>(&s.u.part2[pg][1][j0]) =
                make_float4(r01.x, r01.y, r23.x, r23.y);
        }
        __syncthreads();   // S3

        // ---- phase 2 combine + activation (all 1024 threads, 1 col each) ----
        {
            int j = t;
            int gate = j >> 8, h = j & 255;
            float z0 = s.u.part2[0][0][j] + s.u.part2[1][0][j]
                     + s.u.part2[2][0][j] + s.u.part2[3][0][j];
            float z1 = s.u.part2[0][1][j] + s.u.part2[1][1][j]
                     + s.u.part2[2][1][j] + s.u.part2[3][1][j];
            float bia = s.bsm[j];
            z0 += bia; z1 += bia;
            float v0, v1;
            if (gate == 2) { v0 = fast_tanh(z0);    v1 = fast_tanh(z1); }
            else           { v0 = fast_sigmoid(z0); v1 = fast_sigmoid(z1); }
            s.gsm[gate][0][h] = v0;
            s.gsm[gate][1][h] = v1;
        }
        __syncthreads();   // S4

        // ---- phase 3: cell update + output ----
        if (t < BC * HID) {
            int b = t >> 8, h = t & 255;
            float fg = s.gsm[0][b][h];
            float ig = s.gsm[1][b][h];
            float gg = s.gsm[2][b][h];
            float og = s.gsm[3][b][h];
            float c  = fmaf(fg, s.csm[b][h], ig * gg);
            s.csm[b][h] = c;
            float hn = og * fast_tanh(c);
            s.comb[b][DIN + h]  = hn;
            s.combh[b][DIN + h] = __float2half(hn);
            out[(size_t)step * BATCH * HID + (size_t)(cta * BC + b) * HID + h] = hn;
        }
        // wraparound ordering: S0 at top of next iter orders phase-3 writes
        // (comb/combh/csm) before phase-1 reads.
    }

    // ---- final hx, cx ----
    if (t < BC * HID) {
        int b = t >> 8, h = t & 255;
        int bgl = cta * BC + b;
        size_t base = (size_t)T_STEPS * BATCH * HID;
        out[base + (size_t)bgl * HID + h]                        = s.comb[b][DIN + h];
        out[base + (size_t)BATCH * HID + (size_t)bgl * HID + h]  = s.csm[b][h];
    }
}

extern "C" void kernel_launch(void* const* d_in, const int* in_sizes, int n_in,
                              void* d_out, int out_size) {
    const float* x     = (const float*)d_in[0];
    const float* proto = (const float*)d_in[1];
    const float* Wf    = (const float*)d_in[2];
    const float* bf    = (const float*)d_in[3];
    const float* Wi    = (const float*)d_in[4];
    const float* bi    = (const float*)d_in[5];
    const float* Wg    = (const float*)d_in[6];
    const float* bg    = (const float*)d_in[7];
    const float* Wo    = (const float*)d_in[8];
    const float* bo    = (const float*)d_in[9];
    float* out = (float*)d_out;

    cudaFuncSetAttribute(qlstm_kernel, cudaFuncAttributeMaxDynamicSharedMemorySize,
                         (int)sizeof(Smem));

    prep_kernel<<<128, 256>>>(proto, Wf, Wi, Wg, Wo);
    qlstm_kernel<<<NCTA, NTHREADS, sizeof(Smem)>>>(x, bf, bi, bg, bo, out);
}